// round 1
// baseline (speedup 1.0000x reference)
#include <cuda_runtime.h>

#define BB 2
#define NN 1024
#define DD 3
#define F1 32
#define F2 64

// Scratch (no allocs allowed)
__device__ float g_a1[BB*NN*F1];
__device__ float g_c1[BB*NN*F1];
__device__ float g_a2[BB*NN*F2];
__device__ float g_c2[BB*NN*F2];
__device__ float g_a3[BB*NN*DD];
__device__ float g_c3[BB*NN*DD];

// ---------------------------------------------------------------------------
// K1: per point, x (3) -> a1 (32, bias folded) and c1 (32)
// ---------------------------------------------------------------------------
__global__ __launch_bounds__(256) void k1_proj(
    const float* __restrict__ x,
    const float* __restrict__ W1,
    const float* __restrict__ b1)
{
    __shared__ float sW[6*F1];
    __shared__ float sb[F1];
    int tid = threadIdx.x;
    if (tid < 6*F1) sW[tid] = W1[tid];
    if (tid < F1)   sb[tid] = b1[tid];
    __syncthreads();

    int p = blockIdx.x * blockDim.x + tid;      // global point index [0, B*N)
    if (p >= BB*NN) return;
    float x0 = x[p*3+0], x1 = x[p*3+1], x2 = x[p*3+2];
#pragma unroll
    for (int f = 0; f < F1; f++) {
        float a = x0*sW[0*F1+f] + x1*sW[1*F1+f] + x2*sW[2*F1+f] + sb[f];
        float c = x0*sW[3*F1+f] + x1*sW[4*F1+f] + x2*sW[5*F1+f];
        g_a1[p*F1+f] = a;
        g_c1[p*F1+f] = c;
    }
}

// ---------------------------------------------------------------------------
// Pairwise relu-mean + fused projection to next stage's (a, c)
//   h_i[f] = (1/(N-1)) * sum_{j != i} relu(a_i[f] + c_j[f])
//   a_next_i = h_i @ Wtop + bnext   (bias folded)
//   c_next_i = h_i @ Wbot
// Layout: TI points per block. threads = IG * FG.
//   thread (ig, fg) owns IPT = TI/IG points and FPT = F/FG = 4 features.
//   All threads stream the same j tile from shared; no cross-thread reduce.
// ---------------------------------------------------------------------------
template<int F, int TI, int IG, int FG, int JT, int FN>
__global__ __launch_bounds__(IG*FG) void pair_kernel(
    const float* __restrict__ a,      // [B*N*F], bias folded
    const float* __restrict__ c,      // [B*N*F]
    const float* __restrict__ Wtop,   // [F*FN]
    const float* __restrict__ Wbot,   // [F*FN]
    const float* __restrict__ bnext,  // [FN]
    float* __restrict__ a_next,       // [B*N*FN]
    float* __restrict__ c_next)       // [B*N*FN]
{
    constexpr int IPT = TI / IG;
    constexpr int FPT = F / FG;       // must be 4
    constexpr int NT  = IG * FG;
    static_assert(FPT == 4, "FPT must be 4");

    __shared__ __align__(16) float c_sh[JT][F];
    __shared__ float h_sh[TI][F + 1];   // +1 pad: avoid bank conflicts

    int tid = threadIdx.x;
    int fg  = tid % FG;
    int ig  = tid / FG;
    int i_base = blockIdx.x * TI;       // TI divides N -> never spans batches
    int b = i_base / NN;
    int f0 = fg * FPT;

    float u[IPT][FPT];
    float acc[IPT][FPT];
#pragma unroll
    for (int ii = 0; ii < IPT; ii++) {
        int gi = i_base + ig*IPT + ii;
#pragma unroll
        for (int k = 0; k < FPT; k++) {
            u[ii][k]   = a[gi*F + f0 + k];
            acc[ii][k] = 0.0f;
        }
    }

    const float4* csrc = reinterpret_cast<const float4*>(c + (size_t)b*NN*F);
    float4* cdst = reinterpret_cast<float4*>(&c_sh[0][0]);
    constexpr int V = JT*F/4;

    for (int jt = 0; jt < NN; jt += JT) {
        __syncthreads();
#pragma unroll
        for (int k = tid; k < V; k += NT)
            cdst[k] = csrc[jt*(F/4) + k];
        __syncthreads();

#pragma unroll 4
        for (int j = 0; j < JT; j++) {
            float4 cv = *reinterpret_cast<const float4*>(&c_sh[j][f0]);
#pragma unroll
            for (int ii = 0; ii < IPT; ii++) {
                acc[ii][0] += fmaxf(u[ii][0] + cv.x, 0.0f);
                acc[ii][1] += fmaxf(u[ii][1] + cv.y, 0.0f);
                acc[ii][2] += fmaxf(u[ii][2] + cv.z, 0.0f);
                acc[ii][3] += fmaxf(u[ii][3] + cv.w, 0.0f);
            }
        }
    }

    // subtract self term, scale, stage h into shared
    const float scale = 1.0f / (float)(NN - 1);
#pragma unroll
    for (int ii = 0; ii < IPT; ii++) {
        int li = ig*IPT + ii;
        int gi = i_base + li;
#pragma unroll
        for (int k = 0; k < FPT; k++) {
            float self = fmaxf(u[ii][k] + c[gi*F + f0 + k], 0.0f);
            h_sh[li][f0 + k] = (acc[ii][k] - self) * scale;
        }
    }
    __syncthreads();

    // fused projection to next stage
    for (int o = tid; o < TI*FN; o += NT) {
        int li = o / FN;
        int fn = o % FN;
        float sa = bnext[fn];
        float sc = 0.0f;
#pragma unroll
        for (int f = 0; f < F; f++) {
            float hv = h_sh[li][f];
            sa += hv * Wtop[f*FN + fn];
            sc += hv * Wbot[f*FN + fn];
        }
        int gi = i_base + li;
        a_next[gi*FN + fn] = sa;
        c_next[gi*FN + fn] = sc;
    }
}

// ---------------------------------------------------------------------------
// K4: block 3 has no relu -> closed form:
//   out_i = a3_i (b3 already folded) + (sum_j c3_j - c3_i) / (N-1)
// one block per batch, 1024 threads
// ---------------------------------------------------------------------------
__global__ __launch_bounds__(1024) void k4_final(float* __restrict__ out)
{
    int b = blockIdx.x;
    int i = threadIdx.x;
    __shared__ float s0[NN], s1[NN], s2[NN];

    int gi = b*NN + i;
    float c0 = g_c3[gi*3+0];
    float c1 = g_c3[gi*3+1];
    float c2 = g_c3[gi*3+2];
    s0[i] = c0; s1[i] = c1; s2[i] = c2;
    __syncthreads();

#pragma unroll
    for (int st = NN/2; st > 0; st >>= 1) {
        if (i < st) { s0[i] += s0[i+st]; s1[i] += s1[i+st]; s2[i] += s2[i+st]; }
        __syncthreads();
    }
    float S0 = s0[0], S1 = s1[0], S2 = s2[0];

    const float scale = 1.0f / (float)(NN - 1);
    out[gi*3+0] = g_a3[gi*3+0] + (S0 - c0) * scale;
    out[gi*3+1] = g_a3[gi*3+1] + (S1 - c1) * scale;
    out[gi*3+2] = g_a3[gi*3+2] + (S2 - c2) * scale;
}

// ---------------------------------------------------------------------------
extern "C" void kernel_launch(void* const* d_in, const int* in_sizes, int n_in,
                              void* d_out, int out_size)
{
    const float* x  = (const float*)d_in[0];   // (2, 3072)
    const float* W1 = (const float*)d_in[1];   // (6, 32)
    const float* b1 = (const float*)d_in[2];   // (32,)
    const float* W2 = (const float*)d_in[3];   // (64, 64)
    const float* b2 = (const float*)d_in[4];   // (64,)
    const float* W3 = (const float*)d_in[5];   // (128, 3)
    const float* b3 = (const float*)d_in[6];   // (3,)
    float* out = (float*)d_out;

    float *a1, *c1, *a2, *c2, *a3, *c3;
    cudaGetSymbolAddress((void**)&a1, g_a1);
    cudaGetSymbolAddress((void**)&c1, g_c1);
    cudaGetSymbolAddress((void**)&a2, g_a2);
    cudaGetSymbolAddress((void**)&c2, g_c2);
    cudaGetSymbolAddress((void**)&a3, g_a3);
    cudaGetSymbolAddress((void**)&c3, g_c3);

    // K1: x -> a1, c1
    k1_proj<<<(BB*NN + 255)/256, 256>>>(x, W1, b1);

    // K2: pairwise F=32 (relu) + project to a2/c2 via W2 (top rows 0..31, bot 32..63)
    pair_kernel<F1, 16, 16, 8, 256, F2><<<BB*NN/16, 128>>>(
        a1, c1, W2, W2 + 32*F2, b2, a2, c2);

    // K3: pairwise F=64 (relu) + project to a3/c3 via W3 (top rows 0..63, bot 64..127)
    pair_kernel<F2, 16, 8, 16, 128, DD><<<BB*NN/16, 128>>>(
        a2, c2, W3, W3 + 64*DD, b3, a3, c3);

    // K4: closed-form block 3 (no relu) -> output
    k4_final<<<BB, NN>>>(out);
}

// round 2
// speedup vs baseline: 1.0689x; 1.0689x over previous
#include <cuda_runtime.h>

#define BB 2
#define NN 1024
#define DD 3
#define F1 32
#define F2 64

// Scratch (no allocs allowed)
__device__ float g_a1[BB*NN*F1];
__device__ float g_c1[BB*NN*F1];
__device__ float g_a2[BB*NN*F2];
__device__ float g_c2[BB*NN*F2];
__device__ float g_a3[BB*NN*DD];
__device__ float g_c3[BB*NN*DD];

// acc += max(u + (ca,cb), 0), elementwise on 2 packed lanes.
// Packed adds go to the fma pipe (1 instr / 2 lanes); the two FMNMX go to
// the alu pipe. b64 pack/unpack movs should be elided by ptxas reg pairing.
__device__ __forceinline__ void pk_acc_relu(float2& acc, float2 u, float ca, float cb)
{
    asm volatile(
        "{\n\t"
        ".reg .b64 ru, rc, rs, ra;\n\t"
        ".reg .f32 s0, s1;\n\t"
        "mov.b64 ru, {%4, %5};\n\t"
        "mov.b64 rc, {%6, %7};\n\t"
        "add.rn.f32x2 rs, ru, rc;\n\t"
        "mov.b64 {s0, s1}, rs;\n\t"
        "max.f32 s0, s0, 0f00000000;\n\t"
        "max.f32 s1, s1, 0f00000000;\n\t"
        "mov.b64 rs, {s0, s1};\n\t"
        "mov.b64 ra, {%2, %3};\n\t"
        "add.rn.f32x2 ra, ra, rs;\n\t"
        "mov.b64 {%0, %1}, ra;\n\t"
        "}"
        : "=f"(acc.x), "=f"(acc.y)
        : "f"(acc.x), "f"(acc.y), "f"(u.x), "f"(u.y), "f"(ca), "f"(cb));
}

// ---------------------------------------------------------------------------
// K1: per point, x (3) -> a1 (32, bias folded) and c1 (32)
// ---------------------------------------------------------------------------
__global__ __launch_bounds__(256) void k1_proj(
    const float* __restrict__ x,
    const float* __restrict__ W1,
    const float* __restrict__ b1)
{
    __shared__ float sW[6*F1];
    __shared__ float sb[F1];
    int tid = threadIdx.x;
    if (tid < 6*F1) sW[tid] = W1[tid];
    if (tid < F1)   sb[tid] = b1[tid];
    __syncthreads();

    int p = blockIdx.x * blockDim.x + tid;
    if (p >= BB*NN) return;
    float x0 = x[p*3+0], x1 = x[p*3+1], x2 = x[p*3+2];
#pragma unroll
    for (int f = 0; f < F1; f++) {
        float a = x0*sW[0*F1+f] + x1*sW[1*F1+f] + x2*sW[2*F1+f] + sb[f];
        float c = x0*sW[3*F1+f] + x1*sW[4*F1+f] + x2*sW[5*F1+f];
        g_a1[p*F1+f] = a;
        g_c1[p*F1+f] = c;
    }
}

// ---------------------------------------------------------------------------
// Pairwise relu-mean + fused projection to next stage's (a, c)
//   h_i[f] = (1/(N-1)) * sum_{j != i} relu(a_i[f] + c_j[f])
//   a_next_i = h_i @ W[0:F]   + bnext
//   c_next_i = h_i @ W[F:2F]
// 256 threads: FG feature-groups x IG=256/FG point-groups. IPT = 1 point
// per thread (TI == IG). FPT = F/FG features per thread, processed as
// PL = FPT/2 packed f32x2 lanes.
// ---------------------------------------------------------------------------
template<int F, int TI, int FG, int JT, int FN>
__global__ __launch_bounds__(256) void pair_kernel(
    const float* __restrict__ a,      // [B*N*F], bias folded
    const float* __restrict__ c,      // [B*N*F]
    const float* __restrict__ W,      // [2F*FN] top rows then bottom rows
    const float* __restrict__ bnext,  // [FN]
    float* __restrict__ a_next,       // [B*N*FN]
    float* __restrict__ c_next)       // [B*N*FN]
{
    constexpr int NT  = 256;
    constexpr int FPT = F / FG;
    constexpr int PL  = FPT / 2;
    constexpr int IG  = NT / FG;
    static_assert(IG == TI, "one point per thread");
    static_assert(PL >= 1 && PL <= 2, "PL in {1,2}");

    __shared__ __align__(16) float c_sh[JT][F];
    __shared__ float h_sh[TI][F + 1];
    __shared__ float w_sh[2*F*FN];
    __shared__ float bn_sh[FN];

    int tid = threadIdx.x;
    int fg  = tid % FG;
    int ig  = tid / FG;
    int i_base = blockIdx.x * TI;
    int b = i_base / NN;
    int f0 = fg * FPT;
    int gi = i_base + ig;

    // stage weights
    for (int k = tid; k < 2*F*FN; k += NT) w_sh[k] = W[k];
    if (tid < FN) bn_sh[tid] = bnext[tid];

    float2 u[PL], acc[PL];
#pragma unroll
    for (int p = 0; p < PL; p++) {
        u[p]   = *reinterpret_cast<const float2*>(&a[gi*F + f0 + 2*p]);
        acc[p] = make_float2(0.0f, 0.0f);
    }

    const float4* csrc = reinterpret_cast<const float4*>(c + (size_t)b*NN*F);
    float4* cdst = reinterpret_cast<float4*>(&c_sh[0][0]);
    constexpr int V = JT*F/4;

    for (int jt = 0; jt < NN; jt += JT) {
        __syncthreads();
#pragma unroll
        for (int k = tid; k < V; k += NT)
            cdst[k] = csrc[jt*(F/4) + k];
        __syncthreads();

#pragma unroll 8
        for (int j = 0; j < JT; j++) {
            if (PL == 2) {
                float4 cv = *reinterpret_cast<const float4*>(&c_sh[j][f0]);
                pk_acc_relu(acc[0], u[0], cv.x, cv.y);
                pk_acc_relu(acc[1], u[1], cv.z, cv.w);
            } else {
                float2 cv = *reinterpret_cast<const float2*>(&c_sh[j][f0]);
                pk_acc_relu(acc[0], u[0], cv.x, cv.y);
            }
        }
    }

    // subtract self term, scale, stage h into shared
    const float scale = 1.0f / (float)(NN - 1);
#pragma unroll
    for (int p = 0; p < PL; p++) {
        float2 cs = *reinterpret_cast<const float2*>(&c[gi*F + f0 + 2*p]);
        float s0 = fmaxf(u[p].x + cs.x, 0.0f);
        float s1 = fmaxf(u[p].y + cs.y, 0.0f);
        h_sh[ig][f0 + 2*p + 0] = (acc[p].x - s0) * scale;
        h_sh[ig][f0 + 2*p + 1] = (acc[p].y - s1) * scale;
    }
    __syncthreads();

    // fused projection to next stage (W staged in shared)
    for (int o = tid; o < TI*FN; o += NT) {
        int li = o / FN;
        int fn = o % FN;
        float sa = bn_sh[fn];
        float sc = 0.0f;
#pragma unroll
        for (int f = 0; f < F; f++) {
            float hv = h_sh[li][f];
            sa += hv * w_sh[f*FN + fn];
            sc += hv * w_sh[(F + f)*FN + fn];
        }
        int go = i_base + li;
        a_next[go*FN + fn] = sa;
        c_next[go*FN + fn] = sc;
    }
}

// ---------------------------------------------------------------------------
// K4: block 3 has no relu -> closed form:
//   out_i = a3_i (b3 folded) + (sum_j c3_j - c3_i) / (N-1)
// one block per batch; shfl-butterfly + one cross-warp step.
// ---------------------------------------------------------------------------
__global__ __launch_bounds__(1024) void k4_final(float* __restrict__ out)
{
    int b = blockIdx.x;
    int i = threadIdx.x;
    int gi = b*NN + i;

    float c0 = g_c3[gi*3+0];
    float c1 = g_c3[gi*3+1];
    float c2 = g_c3[gi*3+2];

    float s0 = c0, s1 = c1, s2 = c2;
#pragma unroll
    for (int o = 16; o > 0; o >>= 1) {
        s0 += __shfl_xor_sync(0xffffffffu, s0, o);
        s1 += __shfl_xor_sync(0xffffffffu, s1, o);
        s2 += __shfl_xor_sync(0xffffffffu, s2, o);
    }

    __shared__ float p0[32], p1[32], p2[32];
    int w = i >> 5, l = i & 31;
    if (l == 0) { p0[w] = s0; p1[w] = s1; p2[w] = s2; }
    __syncthreads();

    if (w == 0) {
        s0 = p0[l]; s1 = p1[l]; s2 = p2[l];
#pragma unroll
        for (int o = 16; o > 0; o >>= 1) {
            s0 += __shfl_xor_sync(0xffffffffu, s0, o);
            s1 += __shfl_xor_sync(0xffffffffu, s1, o);
            s2 += __shfl_xor_sync(0xffffffffu, s2, o);
        }
        if (l == 0) { p0[0] = s0; p1[0] = s1; p2[0] = s2; }
    }
    __syncthreads();

    float S0 = p0[0], S1 = p1[0], S2 = p2[0];
    const float scale = 1.0f / (float)(NN - 1);
    out[gi*3+0] = g_a3[gi*3+0] + (S0 - c0) * scale;
    out[gi*3+1] = g_a3[gi*3+1] + (S1 - c1) * scale;
    out[gi*3+2] = g_a3[gi*3+2] + (S2 - c2) * scale;
}

// ---------------------------------------------------------------------------
extern "C" void kernel_launch(void* const* d_in, const int* in_sizes, int n_in,
                              void* d_out, int out_size)
{
    const float* x  = (const float*)d_in[0];   // (2, 3072)
    const float* W1 = (const float*)d_in[1];   // (6, 32)
    const float* b1 = (const float*)d_in[2];   // (32,)
    const float* W2 = (const float*)d_in[3];   // (64, 64)
    const float* b2 = (const float*)d_in[4];   // (64,)
    const float* W3 = (const float*)d_in[5];   // (128, 3)
    const float* b3 = (const float*)d_in[6];   // (3,)
    float* out = (float*)d_out;

    float *a1, *c1, *a2, *c2, *a3, *c3;
    cudaGetSymbolAddress((void**)&a1, g_a1);
    cudaGetSymbolAddress((void**)&c1, g_c1);
    cudaGetSymbolAddress((void**)&a2, g_a2);
    cudaGetSymbolAddress((void**)&c2, g_c2);
    cudaGetSymbolAddress((void**)&a3, g_a3);
    cudaGetSymbolAddress((void**)&c3, g_c3);

    // K1: x -> a1, c1
    k1_proj<<<(BB*NN + 255)/256, 256>>>(x, W1, b1);

    // K2: pairwise F=32 (relu) + project to a2/c2 via W2
    // FG=16 -> FPT=2 (1 packed lane), IG=16=TI, JT=256 (4 tiles)
    pair_kernel<F1, 16, 16, 256, F2><<<BB*NN/16, 256>>>(
        a1, c1, W2, b2, a2, c2);

    // K3: pairwise F=64 (relu) + project to a3/c3 via W3
    // FG=16 -> FPT=4 (2 packed lanes), IG=16=TI, JT=128 (8 tiles)
    pair_kernel<F2, 16, 16, 128, DD><<<BB*NN/16, 256>>>(
        a2, c2, W3, b3, a3, c3);

    // K4: closed-form block 3 (no relu) -> output
    k4_final<<<BB, NN>>>(out);
}

// round 3
// speedup vs baseline: 2.5284x; 2.3654x over previous
#include <cuda_runtime.h>

#define BB 2
#define NN 1024
#define DD 3
#define F1 32
#define F2 64
#define NTH 512

// Scratch (no allocs allowed). Transposed layouts: [batch][feature][point]
__device__ float g_h1[BB*F1*NN];
__device__ float g_h2[BB*F2*NN];
__device__ float g_Hsum[BB*F2];

// ---------------------------------------------------------------------------
// In-shared bitonic sort, ascending, NN=1024 elements, NTH=512 threads
// (each thread handles exactly one compare-exchange per phase; 55 phases)
// ---------------------------------------------------------------------------
__device__ __forceinline__ void bitonic_sort(float* s, int tid)
{
#pragma unroll
    for (int k = 2; k <= NN; k <<= 1) {
#pragma unroll
        for (int j = k >> 1; j > 0; j >>= 1) {
            __syncthreads();
            int i = 2*tid - (tid & (j - 1));   // (i & j) == 0
            int p = i + j;
            float x0 = s[i], x1 = s[p];
            bool up = ((i & k) == 0);
            if ((x0 > x1) == up) { s[i] = x1; s[p] = x0; }
        }
    }
    __syncthreads();
}

// exclusive prefix sum of s[0..NN) into P[0..NN], P[NN] = total
__device__ __forceinline__ void exclusive_scan(const float* s, float* P,
                                               float* wsum, int tid)
{
    int lane = tid & 31, wid = tid >> 5;
    float v0 = s[2*tid], v1 = s[2*tid+1];
    float ps = v0 + v1;
    float incl = ps;
#pragma unroll
    for (int o = 1; o < 32; o <<= 1) {
        float n = __shfl_up_sync(0xffffffffu, incl, o);
        if (lane >= o) incl += n;
    }
    if (lane == 31) wsum[wid] = incl;
    __syncthreads();
    if (tid < 16) {
        float w = wsum[tid];
        float i2 = w;
#pragma unroll
        for (int o = 1; o < 16; o <<= 1) {
            float n = __shfl_up_sync(0x0000ffffu, i2, o);
            if (tid >= o) i2 += n;
        }
        wsum[tid] = i2 - w;   // exclusive warp offsets
    }
    __syncthreads();
    float base = wsum[wid] + (incl - ps);
    P[2*tid]   = base;
    P[2*tid+1] = base + v0;
    if (tid == NTH-1) P[NN] = base + ps;
    __syncthreads();
}

// 10-step binary search: first index with s[idx] > q
__device__ __forceinline__ int upper_bound(const float* s, float q)
{
    int lo = 0, hi = NN;
#pragma unroll
    for (int it = 0; it < 10; it++) {
        int mid = (lo + hi) >> 1;
        if (s[mid] <= q) lo = mid + 1; else hi = mid;
    }
    return lo;
}

// ---------------------------------------------------------------------------
// Stage 1: one block per (batch, feature f of 32).
//   a_i = x_i . W1top[:,f] + b1[f];  c_j = x_j . W1bot[:,f]
//   h1[b][f][i] = (a_i*K_i + S_i - relu(a_i + c_i)) / (N-1)
// ---------------------------------------------------------------------------
__global__ __launch_bounds__(NTH) void stage1(
    const float* __restrict__ x,
    const float* __restrict__ W1,
    const float* __restrict__ b1)
{
    __shared__ float A[NN], C[NN], S[NN];
    __shared__ float P[NN+1];
    __shared__ float wsum[16];

    int tid = threadIdx.x;
    int b = blockIdx.x >> 5;
    int f = blockIdx.x & 31;

    float w0 = W1[0*F1+f], w1 = W1[1*F1+f], w2 = W1[2*F1+f];
    float w3 = W1[3*F1+f], w4 = W1[4*F1+f], w5 = W1[5*F1+f];
    float bias = b1[f];
    const float* xb = x + b*NN*DD;

#pragma unroll
    for (int p = tid; p < NN; p += NTH) {
        float x0 = xb[3*p+0], x1 = xb[3*p+1], x2 = xb[3*p+2];
        float a = x0*w0 + x1*w1 + x2*w2 + bias;
        float c = x0*w3 + x1*w4 + x2*w5;
        A[p] = a; C[p] = c; S[p] = c;
    }

    bitonic_sort(S, tid);
    exclusive_scan(S, P, wsum, tid);

    float T = P[NN];
    const float scale = 1.0f / (float)(NN - 1);
    float* hout = g_h1 + (b*F1 + f)*NN;
#pragma unroll
    for (int p = tid; p < NN; p += NTH) {
        float a = A[p];
        int lo = upper_bound(S, -a);
        float cnt = (float)(NN - lo);
        float sum = T - P[lo];
        float self = fmaxf(a + C[p], 0.0f);
        hout[p] = (a*cnt + sum - self) * scale;
    }
}

// ---------------------------------------------------------------------------
// Stage 2: one block per (batch, feature f2 of 64).
//   a_i = h1_i . W2[0:32, f2] + b2[f2];  c_j = h1_j . W2[32:64, f2]
//   h2[b][f2][i] as above; also Hsum[b][f2] = sum_i h2[b][f2][i]
// ---------------------------------------------------------------------------
__global__ __launch_bounds__(NTH) void stage2(
    const float* __restrict__ W2,
    const float* __restrict__ b2)
{
    __shared__ float A[NN], C[NN], S[NN];
    __shared__ float P[NN+1];
    __shared__ float wsum[16];
    __shared__ float wt[F1], wb[F1];

    int tid = threadIdx.x;
    int b = blockIdx.x >> 6;
    int f2 = blockIdx.x & 63;

    if (tid < F1) {
        wt[tid] = W2[tid*F2 + f2];
        wb[tid] = W2[(F1 + tid)*F2 + f2];
    }
    float bias = b2[f2];
    __syncthreads();

    const float* h1b = g_h1 + b*F1*NN;
#pragma unroll
    for (int p = tid; p < NN; p += NTH) {
        float a = bias, c = 0.0f;
#pragma unroll
        for (int f = 0; f < F1; f++) {
            float hv = h1b[f*NN + p];
            a += hv * wt[f];
            c += hv * wb[f];
        }
        A[p] = a; C[p] = c; S[p] = c;
    }

    bitonic_sort(S, tid);
    exclusive_scan(S, P, wsum, tid);

    float T = P[NN];
    const float scale = 1.0f / (float)(NN - 1);
    float* hout = g_h2 + (b*F2 + f2)*NN;
    float hloc = 0.0f;
#pragma unroll
    for (int p = tid; p < NN; p += NTH) {
        float a = A[p];
        int lo = upper_bound(S, -a);
        float cnt = (float)(NN - lo);
        float sum = T - P[lo];
        float self = fmaxf(a + C[p], 0.0f);
        float h = (a*cnt + sum - self) * scale;
        hout[p] = h;
        hloc += h;
    }

    // block-reduce hloc -> Hsum[b][f2]
    __syncthreads();
    int lane = tid & 31, wid = tid >> 5;
#pragma unroll
    for (int o = 16; o > 0; o >>= 1)
        hloc += __shfl_xor_sync(0xffffffffu, hloc, o);
    if (lane == 0) wsum[wid] = hloc;
    __syncthreads();
    if (tid < 16) {
        float v = wsum[tid];
#pragma unroll
        for (int o = 8; o > 0; o >>= 1)
            v += __shfl_xor_sync(0x0000ffffu, v, o);
        if (tid == 0) g_Hsum[b*F2 + f2] = v;
    }
}

// ---------------------------------------------------------------------------
// Final: block 3 has no relu -> fully closed form, fused projection.
//   out_i = (h2_i @ W3top + b3) + ((Hsum_b - h2_i) @ W3bot) / (N-1)
// ---------------------------------------------------------------------------
__global__ __launch_bounds__(256) void final_k(
    float* __restrict__ out,
    const float* __restrict__ W3,
    const float* __restrict__ b3)
{
    __shared__ float w3s[2*F2*DD];   // 384 floats
    __shared__ float Ssh[DD];

    int tid = threadIdx.x;
    int pg = blockIdx.x * 256 + tid;     // 0..2047 (256 divides NN -> uniform b)
    int b = pg >> 10;
    int pi = pg & (NN - 1);

    for (int k = tid; k < 2*F2*DD; k += 256) w3s[k] = W3[k];
    __syncthreads();
    if (tid < DD) {
        float acc = 0.0f;
        const float* Hs = g_Hsum + b*F2;
#pragma unroll
        for (int f = 0; f < F2; f++) acc += Hs[f] * w3s[(F2+f)*DD + tid];
        Ssh[tid] = acc;
    }
    __syncthreads();

    float a0 = b3[0], a1 = b3[1], a2 = b3[2];
    float c0 = 0.0f, c1 = 0.0f, c2 = 0.0f;
    const float* h2b = g_h2 + b*F2*NN;
#pragma unroll
    for (int f = 0; f < F2; f++) {
        float hv = h2b[f*NN + pi];
        a0 += hv * w3s[f*DD+0];
        a1 += hv * w3s[f*DD+1];
        a2 += hv * w3s[f*DD+2];
        c0 += hv * w3s[(F2+f)*DD+0];
        c1 += hv * w3s[(F2+f)*DD+1];
        c2 += hv * w3s[(F2+f)*DD+2];
    }
    const float scale = 1.0f / (float)(NN - 1);
    out[pg*3+0] = a0 + (Ssh[0] - c0) * scale;
    out[pg*3+1] = a1 + (Ssh[1] - c1) * scale;
    out[pg*3+2] = a2 + (Ssh[2] - c2) * scale;
}

// ---------------------------------------------------------------------------
extern "C" void kernel_launch(void* const* d_in, const int* in_sizes, int n_in,
                              void* d_out, int out_size)
{
    const float* x  = (const float*)d_in[0];   // (2, 3072)
    const float* W1 = (const float*)d_in[1];   // (6, 32)
    const float* b1 = (const float*)d_in[2];   // (32,)
    const float* W2 = (const float*)d_in[3];   // (64, 64)
    const float* b2 = (const float*)d_in[4];   // (64,)
    const float* W3 = (const float*)d_in[5];   // (128, 3)
    const float* b3 = (const float*)d_in[6];   // (3,)
    float* out = (float*)d_out;

    stage1<<<BB*F1, NTH>>>(x, W1, b1);         // 64 blocks
    stage2<<<BB*F2, NTH>>>(W2, b2);            // 128 blocks
    final_k<<<BB*NN/256, 256>>>(out, W3, b3);  // 8 blocks
}

// round 4
// speedup vs baseline: 3.0488x; 1.2058x over previous
#include <cuda_runtime.h>

#define BB 2
#define NN 1024
#define DD 3
#define F1 32
#define F2 64
#define NTH 512

// Scratch (no allocs allowed). Transposed layouts: [batch][feature][point]
__device__ float g_h1[BB*F1*NN];
__device__ float g_h2[BB*F2*NN];
__device__ float g_Hsum[BB*F2];

__device__ __forceinline__ float cx(float v, float w, bool take_min) {
    return take_min ? fminf(v, w) : fmaxf(v, w);
}

// ---------------------------------------------------------------------------
// Register/shuffle bitonic sort of 1024 values, 512 threads.
// Thread t holds elements i0=t (r0) and i1=t+512 (r1).
// j<=16  : shfl_xor within warp (40 phases, no barriers)
// j==512 : intra-thread r0<->r1 (1 phase)
// 32<=j<=256 : shared exchange, double-buffered, 1 barrier each (14 phases)
// Result written to SA (ascending).
// ---------------------------------------------------------------------------
__device__ __forceinline__ void sort1024(float& r0, float& r1,
                                         float* SA, float* SB, int t)
{
    const int i0 = t, i1 = t + 512;
    int bsel = 0;
#pragma unroll
    for (int k = 2; k <= 1024; k <<= 1) {
#pragma unroll
        for (int j = k >> 1; j > 0; j >>= 1) {
            if (j == 512) {
                // k=1024: up=true, i0 takes min, i1 takes max
                float lo = fminf(r0, r1), hi = fmaxf(r0, r1);
                r0 = lo; r1 = hi;
            } else if (j >= 32) {
                float* buf = bsel ? SB : SA; bsel ^= 1;
                buf[i0] = r0; buf[i1] = r1;
                __syncthreads();
                float w0 = buf[i0 ^ j], w1 = buf[i1 ^ j];
                bool tm0 = ((i0 & k) == 0) == ((i0 & j) == 0);
                bool tm1 = ((i1 & k) == 0) == ((i1 & j) == 0);
                r0 = cx(r0, w0, tm0);
                r1 = cx(r1, w1, tm1);
            } else {
                float w0 = __shfl_xor_sync(0xffffffffu, r0, j);
                float w1 = __shfl_xor_sync(0xffffffffu, r1, j);
                bool tm0 = ((i0 & k) == 0) == ((i0 & j) == 0);
                bool tm1 = ((i1 & k) == 0) == ((i1 & j) == 0);
                r0 = cx(r0, w0, tm0);
                r1 = cx(r1, w1, tm1);
            }
        }
    }
    __syncthreads();            // insurance vs pending reads of SA
    SA[i0] = r0; SA[i1] = r1;
    __syncthreads();
}

// exclusive prefix sum of SA[0..NN) into P[0..NN], P[NN] = total
__device__ __forceinline__ void exclusive_scan(const float* s, float* P,
                                               float* wsum, int tid)
{
    int lane = tid & 31, wid = tid >> 5;
    float v0 = s[2*tid], v1 = s[2*tid+1];
    float ps = v0 + v1;
    float incl = ps;
#pragma unroll
    for (int o = 1; o < 32; o <<= 1) {
        float n = __shfl_up_sync(0xffffffffu, incl, o);
        if (lane >= o) incl += n;
    }
    if (lane == 31) wsum[wid] = incl;
    __syncthreads();
    if (tid < 16) {
        float w = wsum[tid];
        float i2 = w;
#pragma unroll
        for (int o = 1; o < 16; o <<= 1) {
            float n = __shfl_up_sync(0x0000ffffu, i2, o);
            if (tid >= o) i2 += n;
        }
        wsum[tid] = i2 - w;   // exclusive warp offsets
    }
    __syncthreads();
    float base = wsum[wid] + (incl - ps);
    P[2*tid]   = base;
    P[2*tid+1] = base + v0;
    if (tid == NTH-1) P[NN] = base + ps;
    __syncthreads();
}

// 10-step binary search: first index with s[idx] > q
__device__ __forceinline__ int upper_bound(const float* s, float q)
{
    int lo = 0, hi = NN;
#pragma unroll
    for (int it = 0; it < 10; it++) {
        int mid = (lo + hi) >> 1;
        if (s[mid] <= q) lo = mid + 1; else hi = mid;
    }
    return lo;
}

// ---------------------------------------------------------------------------
// Stage 1: one block per (batch, feature f of 32).
// ---------------------------------------------------------------------------
__global__ __launch_bounds__(NTH) void stage1(
    const float* __restrict__ x,
    const float* __restrict__ W1,
    const float* __restrict__ b1)
{
    __shared__ float SA[NN], SB[NN], Ash[NN], Csh[NN];
    __shared__ float P[NN+1];
    __shared__ float wsum[16];

    int t = threadIdx.x;
    int b = blockIdx.x >> 5;
    int f = blockIdx.x & 31;

    float w0 = W1[0*F1+f], w1 = W1[1*F1+f], w2 = W1[2*F1+f];
    float w3 = W1[3*F1+f], w4 = W1[4*F1+f], w5 = W1[5*F1+f];
    float bias = b1[f];
    const float* xb = x + b*NN*DD;

    float r0, r1;
    {
        int p = t;
        float x0 = xb[3*p+0], x1 = xb[3*p+1], x2 = xb[3*p+2];
        Ash[p] = x0*w0 + x1*w1 + x2*w2 + bias;
        r0     = x0*w3 + x1*w4 + x2*w5;
        Csh[p] = r0;
        p = t + 512;
        x0 = xb[3*p+0]; x1 = xb[3*p+1]; x2 = xb[3*p+2];
        Ash[p] = x0*w0 + x1*w1 + x2*w2 + bias;
        r1     = x0*w3 + x1*w4 + x2*w5;
        Csh[p] = r1;
    }

    sort1024(r0, r1, SA, SB, t);
    exclusive_scan(SA, P, wsum, t);

    float T = P[NN];
    const float scale = 1.0f / (float)(NN - 1);
    float* hout = g_h1 + (b*F1 + f)*NN;
#pragma unroll
    for (int h = 0; h < 2; h++) {
        int p = t + h*512;
        float a = Ash[p];
        int lo = upper_bound(SA, -a);
        float cnt = (float)(NN - lo);
        float sum = T - P[lo];
        float self = fmaxf(a + Csh[p], 0.0f);
        hout[p] = (a*cnt + sum - self) * scale;
    }
}

// ---------------------------------------------------------------------------
// Stage 2: one block per (batch, feature f2 of 64). Also writes Hsum[b][f2].
// ---------------------------------------------------------------------------
__global__ __launch_bounds__(NTH) void stage2(
    const float* __restrict__ W2,
    const float* __restrict__ b2)
{
    __shared__ float SA[NN], SB[NN], Ash[NN], Csh[NN];
    __shared__ float P[NN+1];
    __shared__ float wsum[16];
    __shared__ float wt[F1], wb[F1];

    int t = threadIdx.x;
    int b = blockIdx.x >> 6;
    int f2 = blockIdx.x & 63;

    if (t < F1) {
        wt[t] = W2[t*F2 + f2];
        wb[t] = W2[(F1 + t)*F2 + f2];
    }
    float bias = b2[f2];
    __syncthreads();

    const float* h1b = g_h1 + b*F1*NN;
    float r0, r1;
#pragma unroll
    for (int h = 0; h < 2; h++) {
        int p = t + h*512;
        float a = bias, c = 0.0f;
#pragma unroll
        for (int f = 0; f < F1; f++) {
            float hv = __ldg(&h1b[f*NN + p]);
            a += hv * wt[f];
            c += hv * wb[f];
        }
        Ash[p] = a; Csh[p] = c;
        if (h == 0) r0 = c; else r1 = c;
    }

    sort1024(r0, r1, SA, SB, t);
    exclusive_scan(SA, P, wsum, t);

    float T = P[NN];
    const float scale = 1.0f / (float)(NN - 1);
    float* hout = g_h2 + (b*F2 + f2)*NN;
    float hloc = 0.0f;
#pragma unroll
    for (int h = 0; h < 2; h++) {
        int p = t + h*512;
        float a = Ash[p];
        int lo = upper_bound(SA, -a);
        float cnt = (float)(NN - lo);
        float sum = T - P[lo];
        float self = fmaxf(a + Csh[p], 0.0f);
        float hv = (a*cnt + sum - self) * scale;
        hout[p] = hv;
        hloc += hv;
    }

    // block-reduce hloc -> Hsum[b][f2]
    __syncthreads();
    int lane = t & 31, wid = t >> 5;
#pragma unroll
    for (int o = 16; o > 0; o >>= 1)
        hloc += __shfl_xor_sync(0xffffffffu, hloc, o);
    if (lane == 0) wsum[wid] = hloc;
    __syncthreads();
    if (t < 16) {
        float v = wsum[t];
#pragma unroll
        for (int o = 8; o > 0; o >>= 1)
            v += __shfl_xor_sync(0x0000ffffu, v, o);
        if (t == 0) g_Hsum[b*F2 + f2] = v;
    }
}

// ---------------------------------------------------------------------------
// Final: block 3 has no relu -> fully closed form, fused projection.
//   out_i = (h2_i @ W3top + b3) + ((Hsum_b - h2_i) @ W3bot) / (N-1)
// ---------------------------------------------------------------------------
__global__ __launch_bounds__(256) void final_k(
    float* __restrict__ out,
    const float* __restrict__ W3,
    const float* __restrict__ b3)
{
    __shared__ float w3s[2*F2*DD];   // 384 floats
    __shared__ float Ssh[DD];

    int tid = threadIdx.x;
    int pg = blockIdx.x * 256 + tid;
    int b = pg >> 10;
    int pi = pg & (NN - 1);

    for (int k = tid; k < 2*F2*DD; k += 256) w3s[k] = W3[k];
    __syncthreads();
    if (tid < DD) {
        float acc = 0.0f;
        const float* Hs = g_Hsum + b*F2;
#pragma unroll
        for (int f = 0; f < F2; f++) acc += Hs[f] * w3s[(F2+f)*DD + tid];
        Ssh[tid] = acc;
    }
    __syncthreads();

    float a0 = b3[0], a1 = b3[1], a2 = b3[2];
    float c0 = 0.0f, c1 = 0.0f, c2 = 0.0f;
    const float* h2b = g_h2 + b*F2*NN;
#pragma unroll
    for (int f = 0; f < F2; f++) {
        float hv = h2b[f*NN + pi];
        a0 += hv * w3s[f*DD+0];
        a1 += hv * w3s[f*DD+1];
        a2 += hv * w3s[f*DD+2];
        c0 += hv * w3s[(F2+f)*DD+0];
        c1 += hv * w3s[(F2+f)*DD+1];
        c2 += hv * w3s[(F2+f)*DD+2];
    }
    const float scale = 1.0f / (float)(NN - 1);
    out[pg*3+0] = a0 + (Ssh[0] - c0) * scale;
    out[pg*3+1] = a1 + (Ssh[1] - c1) * scale;
    out[pg*3+2] = a2 + (Ssh[2] - c2) * scale;
}

// ---------------------------------------------------------------------------
extern "C" void kernel_launch(void* const* d_in, const int* in_sizes, int n_in,
                              void* d_out, int out_size)
{
    const float* x  = (const float*)d_in[0];   // (2, 3072)
    const float* W1 = (const float*)d_in[1];   // (6, 32)
    const float* b1 = (const float*)d_in[2];   // (32,)
    const float* W2 = (const float*)d_in[3];   // (64, 64)
    const float* b2 = (const float*)d_in[4];   // (64,)
    const float* W3 = (const float*)d_in[5];   // (128, 3)
    const float* b3 = (const float*)d_in[6];   // (3,)
    float* out = (float*)d_out;

    stage1<<<BB*F1, NTH>>>(x, W1, b1);         // 64 blocks
    stage2<<<BB*F2, NTH>>>(W2, b2);            // 128 blocks
    final_k<<<BB*NN/256, 256>>>(out, W3, b3);  // 8 blocks
}